// round 14
// baseline (speedup 1.0000x reference)
#include <cuda_runtime.h>
#include <cuda_bf16.h>
#include <math.h>
#include <stdint.h>

// ---------------------------------------------------------------------------
// LSTM layer: B=32, T=512, D=1024, H=1024
// k1/k3: bf16x3 split GEMM via mma.sync.
// k2: persistent tensor-core recurrence: HIERARCHICAL atomic barrier
//     (8 groups x 16 + top), quad-buffered staging (1 sync/chunk),
//     3-way split accumulators, direct bf16 state emission, xp preload,
//     double-buffered h.
// ---------------------------------------------------------------------------

#define BB 32
#define TT 512
#define DD 1024
#define HH 1024

typedef unsigned long long u64;

// ---------------- PTX helpers (base-target only) ----------------
__device__ __forceinline__ void cp_async16(void* smem_dst, const void* gsrc) {
    unsigned s = (unsigned)__cvta_generic_to_shared(smem_dst);
    asm volatile("cp.async.cg.shared.global [%0], [%1], 16;" :: "r"(s), "l"(gsrc));
}
#define CP_COMMIT() asm volatile("cp.async.commit_group;")
#define CP_WAIT(n)  asm volatile("cp.async.wait_group %0;" :: "n"(n))

__device__ __forceinline__ uint32_t smem_u32(const void* p) {
    return (uint32_t)__cvta_generic_to_shared(p);
}
__device__ __forceinline__ void ldm_x4(uint32_t* r, uint32_t addr) {
    asm volatile("ldmatrix.sync.aligned.m8n8.x4.shared.b16 {%0,%1,%2,%3}, [%4];"
        : "=r"(r[0]), "=r"(r[1]), "=r"(r[2]), "=r"(r[3]) : "r"(addr));
}
__device__ __forceinline__ void ldm_x2(uint32_t* r, uint32_t addr) {
    asm volatile("ldmatrix.sync.aligned.m8n8.x2.shared.b16 {%0,%1}, [%2];"
        : "=r"(r[0]), "=r"(r[1]) : "r"(addr));
}
__device__ __forceinline__ void mma_bf16(float* d, const uint32_t* a,
                                         uint32_t b0, uint32_t b1) {
    asm volatile(
        "mma.sync.aligned.m16n8k16.row.col.f32.bf16.bf16.f32 "
        "{%0,%1,%2,%3}, {%4,%5,%6,%7}, {%8,%9}, {%0,%1,%2,%3};"
        : "+f"(d[0]), "+f"(d[1]), "+f"(d[2]), "+f"(d[3])
        : "r"(a[0]), "r"(a[1]), "r"(a[2]), "r"(a[3]), "r"(b0), "r"(b1));
}

// ---------------- scratch globals ----------------
__device__ float g_xp[(size_t)TT * BB * 4 * HH];      // 256 MB
__device__ __nv_bfloat16 g_h0[2][(size_t)BB * HH];    // h hi, double buffered
__device__ __nv_bfloat16 g_h1[2][(size_t)BB * HH];    // h lo, double buffered
__device__ unsigned g_cnt[8 * 32];                    // group counters, 128B apart
__device__ unsigned g_top = 0;
__device__ unsigned g_gen = 0;

__device__ __nv_bfloat16 g_A0[(size_t)16384 * 1024];  // A hi (x; then states)
__device__ __nv_bfloat16 g_A1[(size_t)16384 * 1024];  // A lo
__device__ __nv_bfloat16 g_B0[(size_t)4096 * 1024];   // W^T hi  [n][k]
__device__ __nv_bfloat16 g_B1[(size_t)4096 * 1024];   // W^T lo
__device__ __nv_bfloat16 g_Wo0[(size_t)1024 * 1024];  // Wo^T hi
__device__ __nv_bfloat16 g_Wo1[(size_t)1024 * 1024];  // Wo^T lo
__device__ __nv_bfloat16 g_Ut0[(size_t)128 * 8 * 32 * 128];  // U tiled hi
__device__ __nv_bfloat16 g_Ut1[(size_t)128 * 8 * 32 * 128];  // U tiled lo
__device__ float g_bias4[4096];

// ===========================================================================
// Conversion kernels (unchanged)
// ===========================================================================
__global__ void k_conv_x(const float* __restrict__ x)   // grid 16384, block 256
{
    const int m = blockIdx.x;                 // m = t*32 + b
    const float* row = x + ((size_t)(m & 31) * TT + (m >> 5)) * DD;
    const int c = threadIdx.x * 4;
    float4 v = *(const float4*)&row[c];
    __nv_bfloat16 h0 = __float2bfloat16(v.x), h1 = __float2bfloat16(v.y);
    __nv_bfloat16 h2 = __float2bfloat16(v.z), h3 = __float2bfloat16(v.w);
    __nv_bfloat16 l0 = __float2bfloat16(v.x - __bfloat162float(h0));
    __nv_bfloat16 l1 = __float2bfloat16(v.y - __bfloat162float(h1));
    __nv_bfloat16 l2 = __float2bfloat16(v.z - __bfloat162float(h2));
    __nv_bfloat16 l3 = __float2bfloat16(v.w - __bfloat162float(h3));
    size_t o = (size_t)m * 1024 + c;
    *(ushort4*)&g_A0[o] = make_ushort4(*(unsigned short*)&h0, *(unsigned short*)&h1,
                                       *(unsigned short*)&h2, *(unsigned short*)&h3);
    *(ushort4*)&g_A1[o] = make_ushort4(*(unsigned short*)&l0, *(unsigned short*)&l1,
                                       *(unsigned short*)&l2, *(unsigned short*)&l3);
}

__global__ void k_transpose_split(const float* __restrict__ W,
                                  __nv_bfloat16* __restrict__ d0,
                                  __nv_bfloat16* __restrict__ d1,
                                  int orow_base)       // grid (32, 32), block (32,8)
{
    __shared__ float tile[32][33];
    const int kt = blockIdx.x * 32, nt = blockIdx.y * 32;
    const int tx = threadIdx.x, ty = threadIdx.y;
#pragma unroll
    for (int i = 0; i < 4; ++i)
        tile[ty + 8 * i][tx] = W[(size_t)(kt + ty + 8 * i) * 1024 + nt + tx];
    __syncthreads();
#pragma unroll
    for (int i = 0; i < 4; ++i) {
        float v = tile[tx][ty + 8 * i];
        __nv_bfloat16 hi = __float2bfloat16(v);
        __nv_bfloat16 lo = __float2bfloat16(v - __bfloat162float(hi));
        size_t o = (size_t)(orow_base + nt + ty + 8 * i) * 1024 + kt + tx;
        d0[o] = hi; d1[o] = lo;
    }
}

__global__ void k_transpose_split_U(const float* __restrict__ U, int g)
{                                                     // grid (32, 32), block (32,8)
    __shared__ float tile[32][33];
    const int kt = blockIdx.x * 32, nt = blockIdx.y * 32;
    const int tx = threadIdx.x, ty = threadIdx.y;
#pragma unroll
    for (int i = 0; i < 4; ++i)
        tile[ty + 8 * i][tx] = U[(size_t)(kt + ty + 8 * i) * 1024 + nt + tx];
    __syncthreads();
#pragma unroll
    for (int i = 0; i < 4; ++i) {
        float v = tile[tx][ty + 8 * i];
        __nv_bfloat16 hi = __float2bfloat16(v);
        __nv_bfloat16 lo = __float2bfloat16(v - __bfloat162float(hi));
        const int j = nt + ty + 8 * i;
        const int k = kt + tx;
        size_t o = ((size_t)(j >> 3) * 8 + (k >> 7)) * 4096
                 + (size_t)(g * 8 + (j & 7)) * 128 + (k & 127);
        g_Ut0[o] = hi; g_Ut1[o] = lo;
    }
}

__global__ void k_bias_concat(const float* bi, const float* bf_,
                              const float* bg, const float* bc)  // grid 16, block 256
{
    int idx = blockIdx.x * 256 + threadIdx.x;
    int g = idx >> 10, j = idx & 1023;
    const float* b = (g == 0) ? bi : (g == 1) ? bf_ : (g == 2) ? bg : bc;
    g_bias4[idx] = b[j];
}

// ===========================================================================
// bf16x3 GEMM via mma.sync (validated R6 version, unchanged)
// ===========================================================================
#define TROW 80
#define TILE_BYTES (128 * TROW)
#define STAGE_BYTES (4 * TILE_BYTES)
#define GSMEM_BYTES (2 * STAGE_BYTES)

__global__ void __launch_bounds__(256) k_gemm_tc(
    const __nv_bfloat16* __restrict__ A0, const __nv_bfloat16* __restrict__ A1,
    const __nv_bfloat16* __restrict__ B0, const __nv_bfloat16* __restrict__ B1,
    const float* __restrict__ bias, float* __restrict__ outp, int mode)
{
    extern __shared__ char smem[];
    __shared__ float sh_bias[128];

    const int tid = threadIdx.x;
    const int wid = tid >> 5;
    const int lane = tid & 31;
    const int nblk = blockIdx.x * 128;
    const int mblk = blockIdx.y * 128;

    const int wm = (wid >> 1) * 32;
    const int wn = (wid & 1) * 64;

    if (tid < 128) sh_bias[tid] = bias[nblk + tid];

    const char* srcs[4] = {
        (const char*)(A0 + (size_t)mblk * 1024),
        (const char*)(A1 + (size_t)mblk * 1024),
        (const char*)(B0 + (size_t)nblk * 1024),
        (const char*)(B1 + (size_t)nblk * 1024) };

#define LOAD_CHUNK(kc, s) do {                                                  \
        char* stg = smem + (s) * STAGE_BYTES;                                    \
        _Pragma("unroll")                                                        \
        for (int i = 0; i < 8; ++i) {                                            \
            const int ch = tid + i * 256;                                        \
            const int tix = ch >> 9;                                             \
            const int q = ch & 511;                                              \
            const int r = q >> 2;                                                \
            const int cc = q & 3;                                                \
            cp_async16(stg + tix * TILE_BYTES + r * TROW + cc * 16,              \
                       srcs[tix] + (size_t)r * 2048 + (kc) * 64 + cc * 16);      \
        }                                                                        \
        CP_COMMIT();                                                             \
    } while (0)

    float acc[2][8][4];
#pragma unroll
    for (int mt = 0; mt < 2; ++mt)
#pragma unroll
        for (int nb = 0; nb < 8; ++nb)
#pragma unroll
            for (int r = 0; r < 4; ++r) acc[mt][nb][r] = 0.0f;

    LOAD_CHUNK(0, 0);

#pragma unroll 1
    for (int c = 0; c < 32; ++c) {
        const int cur = c & 1;
        if (c + 1 < 32) {
            LOAD_CHUNK(c + 1, cur ^ 1);
            CP_WAIT(1);
        } else {
            CP_WAIT(0);
        }
        __syncthreads();

        const uint32_t stg = smem_u32(smem) + cur * STAGE_BYTES;
        const uint32_t sA0 = stg;
        const uint32_t sA1 = stg + TILE_BYTES;
        const uint32_t sB0 = stg + 2 * TILE_BYTES;
        const uint32_t sB1 = stg + 3 * TILE_BYTES;

#pragma unroll
        for (int kt = 0; kt < 2; ++kt) {
            const uint32_t koff = kt * 32 + (lane >> 4) * 16;
            uint32_t a0f[2][4], a1f[2][4], b0f[4][4], b1f[4][4];
#pragma unroll
            for (int mt = 0; mt < 2; ++mt) {
                const uint32_t rb = (wm + mt * 16 + (lane & 15)) * TROW + koff;
                ldm_x4(a0f[mt], sA0 + rb);
                ldm_x4(a1f[mt], sA1 + rb);
            }
#pragma unroll
            for (int nt = 0; nt < 4; ++nt) {
                const uint32_t rb = (wn + nt * 16 + (lane & 15)) * TROW + koff;
                ldm_x4(b0f[nt], sB0 + rb);
                ldm_x4(b1f[nt], sB1 + rb);
            }
#pragma unroll
            for (int mt = 0; mt < 2; ++mt)
#pragma unroll
                for (int nb = 0; nb < 8; ++nb) {
                    const int nt = nb >> 1, h = nb & 1;
                    mma_bf16(acc[mt][nb], a0f[mt], b0f[nt][h], b0f[nt][h + 2]);
                    mma_bf16(acc[mt][nb], a0f[mt], b1f[nt][h], b1f[nt][h + 2]);
                    mma_bf16(acc[mt][nb], a1f[mt], b0f[nt][h], b0f[nt][h + 2]);
                }
        }
        __syncthreads();
    }

    const int mrow0 = mblk + wm + (lane >> 2);
    const int ncol0 = wn + 2 * (lane & 3);
#pragma unroll
    for (int mt = 0; mt < 2; ++mt)
#pragma unroll
        for (int nb = 0; nb < 8; ++nb) {
            const int n = ncol0 + nb * 8;
            const float bx = sh_bias[n], by = sh_bias[n + 1];
#pragma unroll
            for (int half = 0; half < 2; ++half) {
                const int m = mrow0 + mt * 16 + half * 8;
                float ox = acc[mt][nb][half * 2 + 0] + bx;
                float oy = acc[mt][nb][half * 2 + 1] + by;
                if (mode == 1) { ox = fmaxf(ox, 0.f); oy = fmaxf(oy, 0.f); }
                float* dst;
                if (mode == 0)
                    dst = g_xp + (size_t)m * 4096 + nblk + n;
                else
                    dst = outp + ((size_t)(m & 31) * TT + (m >> 5)) * 1024 + nblk + n;
                *(float2*)dst = make_float2(ox, oy);
            }
        }
}

// ===========================================================================
// Kernel 2: persistent tensor-core recurrence.
// Hierarchical barrier + quad-buffered staging (1 sync/chunk) + 3-way split
// accumulators. 128 blocks x 256 threads, 1 block/SM (~213KB smem).
// ===========================================================================
#define NBLK2 128
#define TROW2 272
#define UHT (32 * TROW2)                /* 8704 per 128k U subtile */
#define UTILE (8 * UHT)                 /* 69632 per matrix */
#define U_OFF 0
#define HTILE (32 * TROW2)              /* 8704 per matrix */
#define HSTAGE (2 * HTILE)              /* 17408 per stage (hi+lo) */
#define NSTG 4
#define STG_OFF (2 * UTILE)             /* 139264 */
#define Z_OFF (STG_OFF + NSTG * HSTAGE) /* 208896 */
#define SMEM2_BYTES (Z_OFF + 32 * 34 * 4)  /* 213248 */

__global__ void __launch_bounds__(256, 1) k_recurrent_tc(
    const __nv_bfloat16* __restrict__ Ut0, const __nv_bfloat16* __restrict__ Ut1)
{
    extern __shared__ char smem[];
    float* shz = (float*)(smem + Z_OFF);

    const int tid = threadIdx.x;
    const int wid = tid >> 5;
    const int lane = tid & 31;
    const int bid = blockIdx.x;
    const int jb8 = bid * 8;

    const int wm = (wid >> 2) * 16;        // m-tile base (0 or 16)
    const int wg = wid & 3;                // gate for this warp
    const uint32_t sb0 = smem_u32(smem);

    // ---- load U tiles into smem once (128KB via cp.async) ----
    {
        const char* u0g = (const char*)Ut0 + (size_t)bid * 65536;
        const char* u1g = (const char*)Ut1 + (size_t)bid * 65536;
#pragma unroll 4
        for (int i = tid; i < 8192; i += 256) {   // 16B units
            const int mat = i >> 12;
            const int rem = i & 4095;
            const int rn = rem >> 4;              // (subtile*32+n)
            const int cc = rem & 15;
            const char* g = (mat ? u1g : u0g) + rn * 256 + cc * 16;
            cp_async16(smem + U_OFF + mat * UTILE + rn * TROW2 + cc * 16, g);
        }
        CP_COMMIT();
        CP_WAIT(0);
    }
    __syncthreads();

    // output identity: (rb, rj) owns (b=rb, j=jb8+rj)
    const int rb = tid >> 3;
    const int rj = tid & 7;
    float cstate = 0.0f;

    // ldmatrix address components
    const int l15 = lane & 15;
    const uint32_t a_row = (uint32_t)(l15 * TROW2 + (lane >> 4) * 16);
    const uint32_t b_row = (uint32_t)((wg * 8 + (l15 & 7)) * TROW2 + ((l15 >> 3) & 1) * 16);

    // h chunk loader: chunk kc (0..7, 128k), stage s, double-buffered source
#define LOADH(kc, s, hb0, hb1) do {                                             \
        char* stg = smem + STG_OFF + (s) * HSTAGE;                               \
        _Pragma("unroll")                                                        \
        for (int i = 0; i < 4; ++i) {                                            \
            const int idx = tid + i * 256;        /* 0..1023 16B units */        \
            const int mat = idx >> 9;                                            \
            const int rem = idx & 511;                                           \
            const int r = rem >> 4;                                              \
            const int cc = rem & 15;                                             \
            const char* src = (mat ? (hb1) : (hb0))                              \
                              + (size_t)r * 2048 + (kc) * 256 + cc * 16;         \
            cp_async16(stg + mat * HTILE + r * TROW2 + cc * 16, src);            \
        }                                                                        \
        CP_COMMIT();                                                             \
    } while (0)

    // preload xp for step 0
    const float* xp0 = g_xp + (size_t)rb * 4096 + jb8 + rj;
    float xpv0 = xp0[0], xpv1 = xp0[1024], xpv2 = xp0[2048], xpv3 = xp0[3072];

    for (int t = 0; t < TT; ++t) {
        float z[4];
        if (t == 0) {
            z[0] = 0.f; z[1] = 0.f; z[2] = 0.f; z[3] = 0.f;
        } else {
            const char* hb0 = (const char*)g_h0[(t + 1) & 1];   // buf (t-1)&1
            const char* hb1 = (const char*)g_h1[(t + 1) & 1];
            float accA[4] = {0.f, 0.f, 0.f, 0.f};
            float accB[4] = {0.f, 0.f, 0.f, 0.f};
            float accC[4] = {0.f, 0.f, 0.f, 0.f};

            LOADH(0, 0, hb0, hb1);
            LOADH(1, 1, hb0, hb1);
#pragma unroll 1
            for (int c = 0; c < 8; ++c) {
                if (c < 6) {
                    LOADH(c + 2, (c + 2) & 3, hb0, hb1);
                    CP_WAIT(2);                  // chunk c's group done
                } else if (c == 6) {
                    CP_WAIT(1);
                } else {
                    CP_WAIT(0);
                }
                __syncthreads();                 // single sync per chunk

                const uint32_t hA0 = sb0 + STG_OFF + (c & 3) * HSTAGE;
                const uint32_t hA1 = hA0 + HTILE;
                const uint32_t uB0 = sb0 + U_OFF + c * UHT;
                const uint32_t uB1 = uB0 + UTILE;

#pragma unroll
                for (int kk = 0; kk < 8; ++kk) {
                    const uint32_t ka = (uint32_t)(wm * TROW2 + kk * 32) + a_row;
                    const uint32_t kb = (uint32_t)(kk * 32) + b_row;
                    uint32_t a0f[4], a1f[4], b0f[2], b1f[2];
                    ldm_x4(a0f, hA0 + ka);
                    ldm_x4(a1f, hA1 + ka);
                    ldm_x2(b0f, uB0 + kb);
                    ldm_x2(b1f, uB1 + kb);
                    mma_bf16(accA, a0f, b0f[0], b0f[1]);
                    mma_bf16(accB, a0f, b1f[0], b1f[1]);
                    mma_bf16(accC, a1f, b0f[0], b0f[1]);
                }
            }

            // combine split products
            float acc[4];
#pragma unroll
            for (int r = 0; r < 4; ++r) acc[r] = accA[r] + accB[r] + accC[r];

            // ---- z exchange: warp w holds (16b x 8n) tile for gate wg ----
            {
                const int brow0 = wm + (lane >> 2);
                const int col0 = wg * 8 + 2 * (lane & 3);
                *(float2*)&shz[brow0 * 34 + col0] = make_float2(acc[0], acc[1]);
                *(float2*)&shz[(brow0 + 8) * 34 + col0] = make_float2(acc[2], acc[3]);
            }
            __syncthreads();

#pragma unroll
            for (int g = 0; g < 4; ++g)
                z[g] = shz[rb * 34 + g * 8 + rj];
        }

        // ---- gates + state update ----
        float zi = z[0] + xpv0;
        float zf = z[1] + xpv1;
        float zg = z[2] + xpv2;
        float zc = z[3] + xpv3;

        float ig = 1.0f / (1.0f + __expf(-zi));
        float fg = 1.0f / (1.0f + __expf(-zf));
        float gg = 1.0f / (1.0f + __expf(-zg));
        float ct = tanhf(zc);
        cstate = fg * cstate + ig * ct;
        float h = gg * tanhf(cstate);

        // states written directly as bf16 hi/lo (consumed by k3)
        __nv_bfloat16 hh = __float2bfloat16(h);
        __nv_bfloat16 hl = __float2bfloat16(h - __bfloat162float(hh));
        const size_t mrow = (size_t)(t * 32 + rb) * 1024 + jb8 + rj;
        g_A0[mrow] = hh;
        g_A1[mrow] = hl;
        const int hbuf = t & 1;
        g_h0[hbuf][(size_t)rb * HH + jb8 + rj] = hh;
        g_h1[hbuf][(size_t)rb * HH + jb8 + rj] = hl;

        // ---- hierarchical grid barrier (tid0 only; 8 groups of 16 + top) ----
        __syncthreads();
        unsigned gen_seen = 0;
        bool releaser = false;
        if (tid == 0) {
            __threadfence();
            gen_seen = *(volatile unsigned*)&g_gen;
            unsigned r = atomicAdd(&g_cnt[(bid >> 4) * 32], 1);
            if (r == 15) {
                unsigned r2 = atomicAdd(&g_top, 1);
                if (r2 == 7) {
                    *(volatile unsigned*)&g_top = 0;
#pragma unroll
                    for (int gg2 = 0; gg2 < 8; ++gg2)
                        *(volatile unsigned*)&g_cnt[gg2 * 32] = 0;
                    __threadfence();
                    atomicExch(&g_gen, gen_seen + 1);
                    releaser = true;
                }
            }
        }
        // preload xp for step t+1 while waiting
        if (t + 1 < TT) {
            const float* xpn = g_xp + ((size_t)(t + 1) * 32 + rb) * 4096 + jb8 + rj;
            xpv0 = xpn[0]; xpv1 = xpn[1024]; xpv2 = xpn[2048]; xpv3 = xpn[3072];
        }
        if (tid == 0 && !releaser) {
            while (*(volatile unsigned*)&g_gen == gen_seen) { }
            __threadfence();
        }
        __syncthreads();
    }
}

// ---------------------------------------------------------------------------
// Launch
// ---------------------------------------------------------------------------
extern "C" void kernel_launch(void* const* d_in, const int* in_sizes, int n_in,
                              void* d_out, int out_size)
{
    const float* x  = (const float*)d_in[0];
    const float* Wi = (const float*)d_in[1];
    const float* Ui = (const float*)d_in[2];
    const float* Wf = (const float*)d_in[3];
    const float* Uf = (const float*)d_in[4];
    const float* Wg = (const float*)d_in[5];
    const float* Ug = (const float*)d_in[6];
    const float* Wc = (const float*)d_in[7];
    const float* Uc = (const float*)d_in[8];
    const float* Wo = (const float*)d_in[9];
    const float* bi = (const float*)d_in[10];
    const float* bf_ = (const float*)d_in[11];
    const float* bg = (const float*)d_in[12];
    const float* bc = (const float*)d_in[13];
    const float* bo = (const float*)d_in[14];
    float* out = (float*)d_out;

    static bool attr_set = false;
    if (!attr_set) {
        cudaFuncSetAttribute(k_recurrent_tc,
                             cudaFuncAttributeMaxDynamicSharedMemorySize, SMEM2_BYTES);
        cudaFuncSetAttribute(k_gemm_tc,
                             cudaFuncAttributeMaxDynamicSharedMemorySize, GSMEM_BYTES);
        attr_set = true;
    }

    static void *pA0 = nullptr, *pA1, *pB0, *pB1, *pWo0, *pWo1, *pbias4, *pUt0, *pUt1;
    if (!pA0) {
        cudaGetSymbolAddress(&pA0, g_A0);
        cudaGetSymbolAddress(&pA1, g_A1);
        cudaGetSymbolAddress(&pB0, g_B0);
        cudaGetSymbolAddress(&pB1, g_B1);
        cudaGetSymbolAddress(&pWo0, g_Wo0);
        cudaGetSymbolAddress(&pWo1, g_Wo1);
        cudaGetSymbolAddress(&pbias4, g_bias4);
        cudaGetSymbolAddress(&pUt0, g_Ut0);
        cudaGetSymbolAddress(&pUt1, g_Ut1);
    }

    // ---- conversions ----
    k_conv_x<<<16384, 256>>>(x);
    dim3 tb(32, 8);
    k_transpose_split<<<dim3(32, 32), tb>>>(Wi, (__nv_bfloat16*)pB0, (__nv_bfloat16*)pB1, 0);
    k_transpose_split<<<dim3(32, 32), tb>>>(Wf, (__nv_bfloat16*)pB0, (__nv_bfloat16*)pB1, 1024);
    k_transpose_split<<<dim3(32, 32), tb>>>(Wg, (__nv_bfloat16*)pB0, (__nv_bfloat16*)pB1, 2048);
    k_transpose_split<<<dim3(32, 32), tb>>>(Wc, (__nv_bfloat16*)pB0, (__nv_bfloat16*)pB1, 3072);
    k_transpose_split<<<dim3(32, 32), tb>>>(Wo, (__nv_bfloat16*)pWo0, (__nv_bfloat16*)pWo1, 0);
    k_transpose_split_U<<<dim3(32, 32), tb>>>(Ui, 0);
    k_transpose_split_U<<<dim3(32, 32), tb>>>(Uf, 1);
    k_transpose_split_U<<<dim3(32, 32), tb>>>(Ug, 2);
    k_transpose_split_U<<<dim3(32, 32), tb>>>(Uc, 3);
    k_bias_concat<<<16, 256>>>(bi, bf_, bg, bc);

    // ---- k1: input projection (tensor cores) ----
    k_gemm_tc<<<dim3(32, 128), 256, GSMEM_BYTES>>>(
        (const __nv_bfloat16*)pA0, (const __nv_bfloat16*)pA1,
        (const __nv_bfloat16*)pB0, (const __nv_bfloat16*)pB1,
        (const float*)pbias4, nullptr, 0);

    // ---- k2: recurrence (tensor cores) ----
    k_recurrent_tc<<<NBLK2, 256, SMEM2_BYTES>>>(
        (const __nv_bfloat16*)pUt0, (const __nv_bfloat16*)pUt1);

    // ---- k3: output projection (states already bf16 hi/lo in g_A0/g_A1) ----
    k_gemm_tc<<<dim3(8, 128), 256, GSMEM_BYTES>>>(
        (const __nv_bfloat16*)pA0, (const __nv_bfloat16*)pA1,
        (const __nv_bfloat16*)pWo0, (const __nv_bfloat16*)pWo1,
        bo, out, 1);
}

// round 16
// speedup vs baseline: 1.0878x; 1.0878x over previous
#include <cuda_runtime.h>
#include <cuda_bf16.h>
#include <math.h>
#include <stdint.h>

// ---------------------------------------------------------------------------
// LSTM layer: B=32, T=512, D=1024, H=1024
// k1/k3: bf16x3 split GEMM via mma.sync.
// k2: persistent tensor-core recurrence (R11 structure) with warp K-split:
//     warp = (mt, ks); each warp computes all 4 gates over kk ≡ {2ks,2ks+1}
//     per chunk -> halved LDSM, 4-way gate ILP; 4-way ks z-reduction.
// ---------------------------------------------------------------------------

#define BB 32
#define TT 512
#define DD 1024
#define HH 1024

typedef unsigned long long u64;

// ---------------- PTX helpers (base-target only) ----------------
__device__ __forceinline__ void cp_async16(void* smem_dst, const void* gsrc) {
    unsigned s = (unsigned)__cvta_generic_to_shared(smem_dst);
    asm volatile("cp.async.cg.shared.global [%0], [%1], 16;" :: "r"(s), "l"(gsrc));
}
#define CP_COMMIT() asm volatile("cp.async.commit_group;")
#define CP_WAIT(n)  asm volatile("cp.async.wait_group %0;" :: "n"(n))

__device__ __forceinline__ uint32_t smem_u32(const void* p) {
    return (uint32_t)__cvta_generic_to_shared(p);
}
__device__ __forceinline__ void ldm_x4(uint32_t* r, uint32_t addr) {
    asm volatile("ldmatrix.sync.aligned.m8n8.x4.shared.b16 {%0,%1,%2,%3}, [%4];"
        : "=r"(r[0]), "=r"(r[1]), "=r"(r[2]), "=r"(r[3]) : "r"(addr));
}
__device__ __forceinline__ void mma_bf16(float* d, const uint32_t* a,
                                         uint32_t b0, uint32_t b1) {
    asm volatile(
        "mma.sync.aligned.m16n8k16.row.col.f32.bf16.bf16.f32 "
        "{%0,%1,%2,%3}, {%4,%5,%6,%7}, {%8,%9}, {%0,%1,%2,%3};"
        : "+f"(d[0]), "+f"(d[1]), "+f"(d[2]), "+f"(d[3])
        : "r"(a[0]), "r"(a[1]), "r"(a[2]), "r"(a[3]), "r"(b0), "r"(b1));
}

// ---------------- scratch globals ----------------
__device__ float g_xp[(size_t)TT * BB * 4 * HH];      // 256 MB
__device__ __nv_bfloat16 g_h0[2][(size_t)BB * HH];    // h hi, double buffered
__device__ __nv_bfloat16 g_h1[2][(size_t)BB * HH];    // h lo, double buffered
__device__ unsigned g_bar_count = 0;
__device__ unsigned g_bar_gen = 0;

__device__ __nv_bfloat16 g_A0[(size_t)16384 * 1024];  // A hi (x; then states)
__device__ __nv_bfloat16 g_A1[(size_t)16384 * 1024];  // A lo
__device__ __nv_bfloat16 g_B0[(size_t)4096 * 1024];   // W^T hi  [n][k]
__device__ __nv_bfloat16 g_B1[(size_t)4096 * 1024];   // W^T lo
__device__ __nv_bfloat16 g_Wo0[(size_t)1024 * 1024];  // Wo^T hi
__device__ __nv_bfloat16 g_Wo1[(size_t)1024 * 1024];  // Wo^T lo
__device__ __nv_bfloat16 g_Ut0[(size_t)128 * 8 * 32 * 128];  // U tiled hi
__device__ __nv_bfloat16 g_Ut1[(size_t)128 * 8 * 32 * 128];  // U tiled lo
__device__ float g_bias4[4096];

// ===========================================================================
// Conversion kernels (unchanged)
// ===========================================================================
__global__ void k_conv_x(const float* __restrict__ x)   // grid 16384, block 256
{
    const int m = blockIdx.x;                 // m = t*32 + b
    const float* row = x + ((size_t)(m & 31) * TT + (m >> 5)) * DD;
    const int c = threadIdx.x * 4;
    float4 v = *(const float4*)&row[c];
    __nv_bfloat16 h0 = __float2bfloat16(v.x), h1 = __float2bfloat16(v.y);
    __nv_bfloat16 h2 = __float2bfloat16(v.z), h3 = __float2bfloat16(v.w);
    __nv_bfloat16 l0 = __float2bfloat16(v.x - __bfloat162float(h0));
    __nv_bfloat16 l1 = __float2bfloat16(v.y - __bfloat162float(h1));
    __nv_bfloat16 l2 = __float2bfloat16(v.z - __bfloat162float(h2));
    __nv_bfloat16 l3 = __float2bfloat16(v.w - __bfloat162float(h3));
    size_t o = (size_t)m * 1024 + c;
    *(ushort4*)&g_A0[o] = make_ushort4(*(unsigned short*)&h0, *(unsigned short*)&h1,
                                       *(unsigned short*)&h2, *(unsigned short*)&h3);
    *(ushort4*)&g_A1[o] = make_ushort4(*(unsigned short*)&l0, *(unsigned short*)&l1,
                                       *(unsigned short*)&l2, *(unsigned short*)&l3);
}

__global__ void k_transpose_split(const float* __restrict__ W,
                                  __nv_bfloat16* __restrict__ d0,
                                  __nv_bfloat16* __restrict__ d1,
                                  int orow_base)       // grid (32, 32), block (32,8)
{
    __shared__ float tile[32][33];
    const int kt = blockIdx.x * 32, nt = blockIdx.y * 32;
    const int tx = threadIdx.x, ty = threadIdx.y;
#pragma unroll
    for (int i = 0; i < 4; ++i)
        tile[ty + 8 * i][tx] = W[(size_t)(kt + ty + 8 * i) * 1024 + nt + tx];
    __syncthreads();
#pragma unroll
    for (int i = 0; i < 4; ++i) {
        float v = tile[tx][ty + 8 * i];
        __nv_bfloat16 hi = __float2bfloat16(v);
        __nv_bfloat16 lo = __float2bfloat16(v - __bfloat162float(hi));
        size_t o = (size_t)(orow_base + nt + ty + 8 * i) * 1024 + kt + tx;
        d0[o] = hi; d1[o] = lo;
    }
}

__global__ void k_transpose_split_U(const float* __restrict__ U, int g)
{                                                     // grid (32, 32), block (32,8)
    __shared__ float tile[32][33];
    const int kt = blockIdx.x * 32, nt = blockIdx.y * 32;
    const int tx = threadIdx.x, ty = threadIdx.y;
#pragma unroll
    for (int i = 0; i < 4; ++i)
        tile[ty + 8 * i][tx] = U[(size_t)(kt + ty + 8 * i) * 1024 + nt + tx];
    __syncthreads();
#pragma unroll
    for (int i = 0; i < 4; ++i) {
        float v = tile[tx][ty + 8 * i];
        __nv_bfloat16 hi = __float2bfloat16(v);
        __nv_bfloat16 lo = __float2bfloat16(v - __bfloat162float(hi));
        const int j = nt + ty + 8 * i;
        const int k = kt + tx;
        size_t o = ((size_t)(j >> 3) * 8 + (k >> 7)) * 4096
                 + (size_t)(g * 8 + (j & 7)) * 128 + (k & 127);
        g_Ut0[o] = hi; g_Ut1[o] = lo;
    }
}

__global__ void k_bias_concat(const float* bi, const float* bf_,
                              const float* bg, const float* bc)  // grid 16, block 256
{
    int idx = blockIdx.x * 256 + threadIdx.x;
    int g = idx >> 10, j = idx & 1023;
    const float* b = (g == 0) ? bi : (g == 1) ? bf_ : (g == 2) ? bg : bc;
    g_bias4[idx] = b[j];
}

// ===========================================================================
// bf16x3 GEMM via mma.sync (validated R6 version, unchanged)
// ===========================================================================
#define TROW 80
#define TILE_BYTES (128 * TROW)
#define STAGE_BYTES (4 * TILE_BYTES)
#define GSMEM_BYTES (2 * STAGE_BYTES)

__global__ void __launch_bounds__(256) k_gemm_tc(
    const __nv_bfloat16* __restrict__ A0, const __nv_bfloat16* __restrict__ A1,
    const __nv_bfloat16* __restrict__ B0, const __nv_bfloat16* __restrict__ B1,
    const float* __restrict__ bias, float* __restrict__ outp, int mode)
{
    extern __shared__ char smem[];
    __shared__ float sh_bias[128];

    const int tid = threadIdx.x;
    const int wid = tid >> 5;
    const int lane = tid & 31;
    const int nblk = blockIdx.x * 128;
    const int mblk = blockIdx.y * 128;

    const int wm = (wid >> 1) * 32;
    const int wn = (wid & 1) * 64;

    if (tid < 128) sh_bias[tid] = bias[nblk + tid];

    const char* srcs[4] = {
        (const char*)(A0 + (size_t)mblk * 1024),
        (const char*)(A1 + (size_t)mblk * 1024),
        (const char*)(B0 + (size_t)nblk * 1024),
        (const char*)(B1 + (size_t)nblk * 1024) };

#define LOAD_CHUNK(kc, s) do {                                                  \
        char* stg = smem + (s) * STAGE_BYTES;                                    \
        _Pragma("unroll")                                                        \
        for (int i = 0; i < 8; ++i) {                                            \
            const int ch = tid + i * 256;                                        \
            const int tix = ch >> 9;                                             \
            const int q = ch & 511;                                              \
            const int r = q >> 2;                                                \
            const int cc = q & 3;                                                \
            cp_async16(stg + tix * TILE_BYTES + r * TROW + cc * 16,              \
                       srcs[tix] + (size_t)r * 2048 + (kc) * 64 + cc * 16);      \
        }                                                                        \
        CP_COMMIT();                                                             \
    } while (0)

    float acc[2][8][4];
#pragma unroll
    for (int mt = 0; mt < 2; ++mt)
#pragma unroll
        for (int nb = 0; nb < 8; ++nb)
#pragma unroll
            for (int r = 0; r < 4; ++r) acc[mt][nb][r] = 0.0f;

    LOAD_CHUNK(0, 0);

#pragma unroll 1
    for (int c = 0; c < 32; ++c) {
        const int cur = c & 1;
        if (c + 1 < 32) {
            LOAD_CHUNK(c + 1, cur ^ 1);
            CP_WAIT(1);
        } else {
            CP_WAIT(0);
        }
        __syncthreads();

        const uint32_t stg = smem_u32(smem) + cur * STAGE_BYTES;
        const uint32_t sA0 = stg;
        const uint32_t sA1 = stg + TILE_BYTES;
        const uint32_t sB0 = stg + 2 * TILE_BYTES;
        const uint32_t sB1 = stg + 3 * TILE_BYTES;

#pragma unroll
        for (int kt = 0; kt < 2; ++kt) {
            const uint32_t koff = kt * 32 + (lane >> 4) * 16;
            uint32_t a0f[2][4], a1f[2][4], b0f[4][4], b1f[4][4];
#pragma unroll
            for (int mt = 0; mt < 2; ++mt) {
                const uint32_t rb = (wm + mt * 16 + (lane & 15)) * TROW + koff;
                ldm_x4(a0f[mt], sA0 + rb);
                ldm_x4(a1f[mt], sA1 + rb);
            }
#pragma unroll
            for (int nt = 0; nt < 4; ++nt) {
                const uint32_t rb = (wn + nt * 16 + (lane & 15)) * TROW + koff;
                ldm_x4(b0f[nt], sB0 + rb);
                ldm_x4(b1f[nt], sB1 + rb);
            }
#pragma unroll
            for (int mt = 0; mt < 2; ++mt)
#pragma unroll
                for (int nb = 0; nb < 8; ++nb) {
                    const int nt = nb >> 1, h = nb & 1;
                    mma_bf16(acc[mt][nb], a0f[mt], b0f[nt][h], b0f[nt][h + 2]);
                    mma_bf16(acc[mt][nb], a0f[mt], b1f[nt][h], b1f[nt][h + 2]);
                    mma_bf16(acc[mt][nb], a1f[mt], b0f[nt][h], b0f[nt][h + 2]);
                }
        }
        __syncthreads();
    }

    const int mrow0 = mblk + wm + (lane >> 2);
    const int ncol0 = wn + 2 * (lane & 3);
#pragma unroll
    for (int mt = 0; mt < 2; ++mt)
#pragma unroll
        for (int nb = 0; nb < 8; ++nb) {
            const int n = ncol0 + nb * 8;
            const float bx = sh_bias[n], by = sh_bias[n + 1];
#pragma unroll
            for (int half = 0; half < 2; ++half) {
                const int m = mrow0 + mt * 16 + half * 8;
                float ox = acc[mt][nb][half * 2 + 0] + bx;
                float oy = acc[mt][nb][half * 2 + 1] + by;
                if (mode == 1) { ox = fmaxf(ox, 0.f); oy = fmaxf(oy, 0.f); }
                float* dst;
                if (mode == 0)
                    dst = g_xp + (size_t)m * 4096 + nblk + n;
                else
                    dst = outp + ((size_t)(m & 31) * TT + (m >> 5)) * 1024 + nblk + n;
                *(float2*)dst = make_float2(ox, oy);
            }
        }
}

// ===========================================================================
// Kernel 2: persistent tensor-core recurrence (R11 + warp K-split).
// Warp wid: mt = wid>>2 (m-tile), ks = wid&3 (K interleave). Each warp
// computes all 4 gates over kk in {2ks, 2ks+1} of each chunk.
// z reduced over 4 ks partials in smem. 128 blocks x 256 thr, 1 blk/SM.
// ===========================================================================
#define NBLK2 128
#define TROW2 272
#define UHT (32 * TROW2)                /* 8704 per 128k U subtile */
#define UTILE (8 * UHT)                 /* 69632 per matrix */
#define U_OFF 0
#define HTILE (32 * TROW2)              /* 8704 per matrix */
#define HSTAGE (2 * HTILE)              /* 17408 per stage (hi+lo) */
#define NSTG 4
#define STG_OFF (2 * UTILE)             /* 139264 */
#define Z_OFF (STG_OFF + NSTG * HSTAGE) /* 208896 */
#define ZKS 1088                        /* floats per ks slab: 32*34 */
#define SMEM2_BYTES (Z_OFF + 4 * ZKS * 4)  /* 226304 */

__device__ __forceinline__ void grid_sync()
{
    __syncthreads();
    if (threadIdx.x == 0) {
        __threadfence();
        unsigned gen = *(volatile unsigned*)&g_bar_gen;
        unsigned t = atomicAdd(&g_bar_count, 1);
        if (t == NBLK2 - 1) {
            g_bar_count = 0;
            __threadfence();
            atomicExch(&g_bar_gen, gen + 1);
        } else {
            while (*(volatile unsigned*)&g_bar_gen == gen) { }
            __threadfence();
        }
    }
    __syncthreads();
}

__global__ void __launch_bounds__(256, 1) k_recurrent_tc(
    const __nv_bfloat16* __restrict__ Ut0, const __nv_bfloat16* __restrict__ Ut1)
{
    extern __shared__ char smem[];
    float* shz = (float*)(smem + Z_OFF);   // [ks:4][row:32][col:34]

    const int tid = threadIdx.x;
    const int wid = tid >> 5;
    const int lane = tid & 31;
    const int bid = blockIdx.x;
    const int jb8 = bid * 8;

    const int wm = (wid >> 2) * 16;        // m-tile base (0 or 16)
    const int ks = wid & 3;                // K interleave slot
    const uint32_t sb0 = smem_u32(smem);

    // ---- load U tiles into smem once (128KB via cp.async) ----
    {
        const char* u0g = (const char*)Ut0 + (size_t)bid * 65536;
        const char* u1g = (const char*)Ut1 + (size_t)bid * 65536;
#pragma unroll 4
        for (int i = tid; i < 8192; i += 256) {   // 16B units
            const int mat = i >> 12;
            const int rem = i & 4095;
            const int rn = rem >> 4;              // (subtile*32+n)
            const int cc = rem & 15;
            const char* g = (mat ? u1g : u0g) + rn * 256 + cc * 16;
            cp_async16(smem + U_OFF + mat * UTILE + rn * TROW2 + cc * 16, g);
        }
        CP_COMMIT();
        CP_WAIT(0);
    }
    __syncthreads();

    // output identity: (rb, rj) owns (b=rb, j=jb8+rj)
    const int rb = tid >> 3;
    const int rj = tid & 7;
    float cstate = 0.0f;

    const int l15 = lane & 15;
    const uint32_t lane_koff = (uint32_t)((lane >> 4) * 16);

    // h chunk loader: chunk kc (0..7, 128k), stage s, double-buffered source
#define LOADH(kc, s, hb0, hb1) do {                                             \
        char* stg = smem + STG_OFF + (s) * HSTAGE;                               \
        _Pragma("unroll")                                                        \
        for (int i = 0; i < 4; ++i) {                                            \
            const int idx = tid + i * 256;        /* 0..1023 16B units */        \
            const int mat = idx >> 9;                                            \
            const int rem = idx & 511;                                           \
            const int r = rem >> 4;                                              \
            const int cc = rem & 15;                                             \
            const char* src = (mat ? (hb1) : (hb0))                              \
                              + (size_t)r * 2048 + (kc) * 256 + cc * 16;         \
            cp_async16(stg + mat * HTILE + r * TROW2 + cc * 16, src);            \
        }                                                                        \
        CP_COMMIT();                                                             \
    } while (0)

    for (int t = 0; t < TT; ++t) {
        // preload xp early so the LDG latency hides under compute
        const float* xp = g_xp + ((size_t)t * 32 + rb) * 4096 + jb8 + rj;
        float xpv0 = xp[0], xpv1 = xp[1024], xpv2 = xp[2048], xpv3 = xp[3072];

        float z[4];
        if (t == 0) {
            z[0] = 0.f; z[1] = 0.f; z[2] = 0.f; z[3] = 0.f;
        } else {
            const char* hb0 = (const char*)g_h0[(t + 1) & 1];   // buf (t-1)&1
            const char* hb1 = (const char*)g_h1[(t + 1) & 1];
            float acc[4][4];                 // per-gate accumulators
#pragma unroll
            for (int g = 0; g < 4; ++g)
#pragma unroll
                for (int r = 0; r < 4; ++r) acc[g][r] = 0.0f;

            LOADH(0, 0, hb0, hb1);
            LOADH(1, 1, hb0, hb1);
#pragma unroll 1
            for (int c = 0; c < 8; ++c) {
                if (c < 6) {
                    LOADH(c + 2, (c + 2) & 3, hb0, hb1);
                    CP_WAIT(2);                  // chunk c's group done
                } else if (c == 6) {
                    CP_WAIT(1);
                } else {
                    CP_WAIT(0);
                }
                __syncthreads();                 // single sync per chunk

                const uint32_t hA0 = sb0 + STG_OFF + (c & 3) * HSTAGE;
                const uint32_t hA1 = hA0 + HTILE;
                const uint32_t uB0 = sb0 + U_OFF + c * UHT;
                const uint32_t uB1 = uB0 + UTILE;

#pragma unroll
                for (int i = 0; i < 2; ++i) {
                    const int kk = ks * 2 + i;               // 0..7
                    const uint32_t koff = (uint32_t)(kk * 32) + lane_koff;
                    const uint32_t ka = (uint32_t)((wm + l15) * TROW2) + koff;
                    uint32_t a0f[4], a1f[4], u0f[2][4], u1f[2][4];
                    ldm_x4(a0f, hA0 + ka);
                    ldm_x4(a1f, hA1 + ka);
#pragma unroll
                    for (int p = 0; p < 2; ++p) {
                        const uint32_t kb = (uint32_t)((p * 16 + l15) * TROW2) + koff;
                        ldm_x4(u0f[p], uB0 + kb);
                        ldm_x4(u1f[p], uB1 + kb);
                    }
#pragma unroll
                    for (int p = 0; p < 2; ++p)
#pragma unroll
                        for (int h = 0; h < 2; ++h) {
                            const int g = p * 2 + h;
                            mma_bf16(acc[g], a0f, u0f[p][h], u0f[p][h + 2]);
                            mma_bf16(acc[g], a0f, u1f[p][h], u1f[p][h + 2]);
                            mma_bf16(acc[g], a1f, u0f[p][h], u0f[p][h + 2]);
                        }
                }
            }

            // ---- z exchange: warp (mt, ks) writes its 16b x 32n fragment ----
            {
                const int r0 = wm + (lane >> 2);
                const int c0 = 2 * (lane & 3);
#pragma unroll
                for (int g = 0; g < 4; ++g) {
                    *(float2*)&shz[ks * ZKS + r0 * 34 + g * 8 + c0] =
                        make_float2(acc[g][0], acc[g][1]);
                    *(float2*)&shz[ks * ZKS + (r0 + 8) * 34 + g * 8 + c0] =
                        make_float2(acc[g][2], acc[g][3]);
                }
            }
            __syncthreads();

#pragma unroll
            for (int g = 0; g < 4; ++g) {
                float s = 0.0f;
#pragma unroll
                for (int q = 0; q < 4; ++q)
                    s += shz[q * ZKS + rb * 34 + g * 8 + rj];
                z[g] = s;
            }
        }

        // ---- gates + state update ----
        float zi = z[0] + xpv0;
        float zf = z[1] + xpv1;
        float zg = z[2] + xpv2;
        float zc = z[3] + xpv3;

        float ig = 1.0f / (1.0f + __expf(-zi));
        float fg = 1.0f / (1.0f + __expf(-zf));
        float gg = 1.0f / (1.0f + __expf(-zg));
        float ct = tanhf(zc);
        cstate = fg * cstate + ig * ct;
        float h = gg * tanhf(cstate);

        // states written directly as bf16 hi/lo (consumed by k3)
        __nv_bfloat16 hh = __float2bfloat16(h);
        __nv_bfloat16 hl = __float2bfloat16(h - __bfloat162float(hh));
        const size_t mrow = (size_t)(t * 32 + rb) * 1024 + jb8 + rj;
        g_A0[mrow] = hh;
        g_A1[mrow] = hl;
        const int hbuf = t & 1;
        g_h0[hbuf][(size_t)rb * HH + jb8 + rj] = hh;
        g_h1[hbuf][(size_t)rb * HH + jb8 + rj] = hl;

        grid_sync();
    }
}

// ---------------------------------------------------------------------------
// Launch
// ---------------------------------------------------------------------------
extern "C" void kernel_launch(void* const* d_in, const int* in_sizes, int n_in,
                              void* d_out, int out_size)
{
    const float* x  = (const float*)d_in[0];
    const float* Wi = (const float*)d_in[1];
    const float* Ui = (const float*)d_in[2];
    const float* Wf = (const float*)d_in[3];
    const float* Uf = (const float*)d_in[4];
    const float* Wg = (const float*)d_in[5];
    const float* Ug = (const float*)d_in[6];
    const float* Wc = (const float*)d_in[7];
    const float* Uc = (const float*)d_in[8];
    const float* Wo = (const float*)d_in[9];
    const float* bi = (const float*)d_in[10];
    const float* bf_ = (const float*)d_in[11];
    const float* bg = (const float*)d_in[12];
    const float* bc = (const float*)d_in[13];
    const float* bo = (const float*)d_in[14];
    float* out = (float*)d_out;

    static bool attr_set = false;
    if (!attr_set) {
        cudaFuncSetAttribute(k_recurrent_tc,
                             cudaFuncAttributeMaxDynamicSharedMemorySize, SMEM2_BYTES);
        cudaFuncSetAttribute(k_gemm_tc,
                             cudaFuncAttributeMaxDynamicSharedMemorySize, GSMEM_BYTES);
        attr_set = true;
    }

    static void *pA0 = nullptr, *pA1, *pB0, *pB1, *pWo0, *pWo1, *pbias4, *pUt0, *pUt1;
    if (!pA0) {
        cudaGetSymbolAddress(&pA0, g_A0);
        cudaGetSymbolAddress(&pA1, g_A1);
        cudaGetSymbolAddress(&pB0, g_B0);
        cudaGetSymbolAddress(&pB1, g_B1);
        cudaGetSymbolAddress(&pWo0, g_Wo0);
        cudaGetSymbolAddress(&pWo1, g_Wo1);
        cudaGetSymbolAddress(&pbias4, g_bias4);
        cudaGetSymbolAddress(&pUt0, g_Ut0);
        cudaGetSymbolAddress(&pUt1, g_Ut1);
    }

    // ---- conversions ----
    k_conv_x<<<16384, 256>>>(x);
    dim3 tb(32, 8);
    k_transpose_split<<<dim3(32, 32), tb>>>(Wi, (__nv_bfloat16*)pB0, (__nv_bfloat16*)pB1, 0);
    k_transpose_split<<<dim3(32, 32), tb>>>(Wf, (__nv_bfloat16*)pB0, (__nv_bfloat16*)pB1, 1024);
    k_transpose_split<<<dim3(32, 32), tb>>>(Wg, (__nv_bfloat16*)pB0, (__nv_bfloat16*)pB1, 2048);
    k_transpose_split<<<dim3(32, 32), tb>>>(Wc, (__nv_bfloat16*)pB0, (__nv_bfloat16*)pB1, 3072);
    k_transpose_split<<<dim3(32, 32), tb>>>(Wo, (__nv_bfloat16*)pWo0, (__nv_bfloat16*)pWo1, 0);
    k_transpose_split_U<<<dim3(32, 32), tb>>>(Ui, 0);
    k_transpose_split_U<<<dim3(32, 32), tb>>>(Uf, 1);
    k_transpose_split_U<<<dim3(32, 32), tb>>>(Ug, 2);
    k_transpose_split_U<<<dim3(32, 32), tb>>>(Uc, 3);
    k_bias_concat<<<16, 256>>>(bi, bf_, bg, bc);

    // ---- k1: input projection (tensor cores) ----
    k_gemm_tc<<<dim3(32, 128), 256, GSMEM_BYTES>>>(
        (const __nv_bfloat16*)pA0, (const __nv_bfloat16*)pA1,
        (const __nv_bfloat16*)pB0, (const __nv_bfloat16*)pB1,
        (const float*)pbias4, nullptr, 0);

    // ---- k2: recurrence (tensor cores) ----
    k_recurrent_tc<<<NBLK2, 256, SMEM2_BYTES>>>(
        (const __nv_bfloat16*)pUt0, (const __nv_bfloat16*)pUt1);

    // ---- k3: output projection (states already bf16 hi/lo in g_A0/g_A1) ----
    k_gemm_tc<<<dim3(8, 128), 256, GSMEM_BYTES>>>(
        (const __nv_bfloat16*)pA0, (const __nv_bfloat16*)pA1,
        (const __nv_bfloat16*)pWo0, (const __nv_bfloat16*)pWo1,
        bo, out, 1);
}